// round 12
// baseline (speedup 1.0000x reference)
#include <cuda_runtime.h>
#include <cuda_bf16.h>
#include <cstdint>

// Problem constants (fixed shapes)
#define BB   4
#define LQ   1024
#define LKV  4096
#define CC   256
#define HH   8
#define DD   32
#define ZZ   1024

#define LOG2E 1.4426950408889634f

// Scratch buffers (allocation-free rule: __device__ globals)
__device__ float g_Q[BB * LQ  * CC];
__device__ float g_K[BB * LKV * CC];
__device__ float g_V[BB * LKV * CC];
__device__ float g_X[BB * LQ  * CC];

// ---------------------------------------------------------------------------
// helpers
// ---------------------------------------------------------------------------
__device__ __forceinline__ uint32_t f2tf(float f) {
    uint32_t u;
    asm("cvt.rna.tf32.f32 %0, %1;" : "=r"(u) : "f"(f));
    return u;
}

// single-instruction MUFU.EX2 regardless of compile flags
__device__ __forceinline__ float ex2(float x) {
    float r;
    asm("ex2.approx.ftz.f32 %0, %1;" : "=f"(r) : "f"(x));
    return r;
}

// D = A(16x8) * B(8x8) + D, tf32 inputs, fp32 accumulate
__device__ __forceinline__ void mma_tf32(float c[4], const uint32_t a[4], const uint32_t b[2]) {
    asm volatile(
        "mma.sync.aligned.m16n8k8.row.col.f32.tf32.tf32.f32 "
        "{%0,%1,%2,%3}, {%4,%5,%6,%7}, {%8,%9}, {%0,%1,%2,%3};"
        : "+f"(c[0]), "+f"(c[1]), "+f"(c[2]), "+f"(c[3])
        : "r"(a[0]), "r"(a[1]), "r"(a[2]), "r"(a[3]), "r"(b[0]), "r"(b[1]));
}

// ---------------------------------------------------------------------------
// tf32 mma GEMM, 64x64 block tile, double-buffered smem, 1 sync per k-iter.
// smem: 2*(64*36)*4 * 2 arrays = 36,864 B  (< 48 KB static limit)
// Y[m][n] = sum_k Xeff[m][k] * W[n][k] (+ bias)
// MODE 0: plain + bias (output projection)
// MODE 1: Xeff = X + ape[m & (LQ-1)]  (q + q_ape; rows-per-batch == LQ)
// 256 threads, 8 warps as 4(m) x 2(n); warp tile 16x32.
// ---------------------------------------------------------------------------
template<int MODE>
__global__ __launch_bounds__(256)
void gemm_mma(const float* __restrict__ X, const float* __restrict__ ape,
              const float* __restrict__ W, const float* __restrict__ bias,
              float* __restrict__ Y)
{
    __shared__ uint32_t sA[2][64][36];
    __shared__ uint32_t sB[2][64][36];

    const int tid  = threadIdx.x;
    const int lane = tid & 31;
    const int w    = tid >> 5;
    const int wm   = w & 3;            // 0..3 (m, 16 rows each)
    const int wn   = w >> 2;           // 0..1 (n, 32 cols each)
    const int g    = lane >> 2;        // 0..7
    const int t    = lane & 3;         // 0..3
    const int m0   = blockIdx.y * 64;
    const int n0   = blockIdx.x * 64;

    const int lrow = tid >> 3;         // 0..31 (rows lrow, lrow+32)
    const int lc4  = (tid & 7) * 4;    // 0..28

    float C[4][4] = {};

    float4 a0, a1, b0, b1;

    auto loadA = [&](int k0, float4& r, int row) {
        const long m = m0 + row;
        r = *reinterpret_cast<const float4*>(&X[m * CC + k0 + lc4]);
        if (MODE == 1) {
            const int lq = (int)m & (LQ - 1);   // rows-per-batch == LQ (power of 2)
            const float4 e = *reinterpret_cast<const float4*>(&ape[(long)lq * CC + k0 + lc4]);
            r.x += e.x; r.y += e.y; r.z += e.z; r.w += e.w;
        }
    };
    auto loadB = [&](int k0, float4& r, int row) {
        r = *reinterpret_cast<const float4*>(&W[(long)(n0 + row) * CC + k0 + lc4]);
    };
    auto store = [&](int buf) {
        sA[buf][lrow     ][lc4 + 0] = f2tf(a0.x); sA[buf][lrow     ][lc4 + 1] = f2tf(a0.y);
        sA[buf][lrow     ][lc4 + 2] = f2tf(a0.z); sA[buf][lrow     ][lc4 + 3] = f2tf(a0.w);
        sA[buf][lrow + 32][lc4 + 0] = f2tf(a1.x); sA[buf][lrow + 32][lc4 + 1] = f2tf(a1.y);
        sA[buf][lrow + 32][lc4 + 2] = f2tf(a1.z); sA[buf][lrow + 32][lc4 + 3] = f2tf(a1.w);
        sB[buf][lrow     ][lc4 + 0] = f2tf(b0.x); sB[buf][lrow     ][lc4 + 1] = f2tf(b0.y);
        sB[buf][lrow     ][lc4 + 2] = f2tf(b0.z); sB[buf][lrow     ][lc4 + 3] = f2tf(b0.w);
        sB[buf][lrow + 32][lc4 + 0] = f2tf(b1.x); sB[buf][lrow + 32][lc4 + 1] = f2tf(b1.y);
        sB[buf][lrow + 32][lc4 + 2] = f2tf(b1.z); sB[buf][lrow + 32][lc4 + 3] = f2tf(b1.w);
    };

    loadA(0, a0, lrow); loadA(0, a1, lrow + 32);
    loadB(0, b0, lrow); loadB(0, b1, lrow + 32);
    store(0);
    __syncthreads();

    const int NK = CC / 32;   // 8
    for (int kt = 0; kt < NK; kt++) {
        const int cur = kt & 1;
        if (kt + 1 < NK) {
            const int k0 = (kt + 1) * 32;
            loadA(k0, a0, lrow); loadA(k0, a1, lrow + 32);
            loadB(k0, b0, lrow); loadB(k0, b1, lrow + 32);
        }

        #pragma unroll
        for (int ks = 0; ks < 4; ks++) {
            uint32_t a[4];
            const int rm = 16 * wm;
            a[0] = sA[cur][rm + g    ][8 * ks + t];
            a[1] = sA[cur][rm + g + 8][8 * ks + t];
            a[2] = sA[cur][rm + g    ][8 * ks + t + 4];
            a[3] = sA[cur][rm + g + 8][8 * ks + t + 4];
            #pragma unroll
            for (int nt = 0; nt < 4; nt++) {
                uint32_t b[2];
                b[0] = sB[cur][32 * wn + 8 * nt + g][8 * ks + t];
                b[1] = sB[cur][32 * wn + 8 * nt + g][8 * ks + t + 4];
                mma_tf32(C[nt], a, b);
            }
        }

        if (kt + 1 < NK) {
            store(cur ^ 1);
            __syncthreads();
        }
    }

    // epilogue
    #pragma unroll
    for (int nt = 0; nt < 4; nt++) {
        const int r0 = m0 + 16 * wm + g;
        const int cc = n0 + 32 * wn + 8 * nt + 2 * t;
        float2 u = make_float2(C[nt][0], C[nt][1]);
        float2 v = make_float2(C[nt][2], C[nt][3]);
        if (MODE == 0) {
            u.x += bias[cc]; u.y += bias[cc + 1];
            v.x += bias[cc]; v.y += bias[cc + 1];
        }
        *reinterpret_cast<float2*>(&Y[(long)r0 * CC + cc]) = u;
        *reinterpret_cast<float2*>(&Y[(long)(r0 + 8) * CC + cc]) = v;
    }
}

// ---------------------------------------------------------------------------
// Fused K+V projection (tf32 mma), 64x64 tiles.
// SINGLE-buffered smem (27,648 B — double-buffering all three tiles would be
// 55,296 B and exceed the 48 KB static-shared limit). Register prefetch keeps
// global-load latency overlapped with the MMA block; 2 barriers per k-iter.
// One pass over kvm = kv (+k_ape rows>=Z), producing K and V projections.
// ---------------------------------------------------------------------------
__global__ __launch_bounds__(256)
void gemm_kv_mma(const float* __restrict__ X, const float* __restrict__ ape,
                 const float* __restrict__ Wk, const float* __restrict__ Wv,
                 float* __restrict__ Yk, float* __restrict__ Yv)
{
    __shared__ uint32_t sA [64][36];
    __shared__ uint32_t sBk[64][36];
    __shared__ uint32_t sBv[64][36];

    const int tid  = threadIdx.x;
    const int lane = tid & 31;
    const int w    = tid >> 5;
    const int wm   = w & 3;
    const int wn   = w >> 2;
    const int g    = lane >> 2;
    const int t    = lane & 3;
    const int m0   = blockIdx.y * 64;
    const int n0   = blockIdx.x * 64;

    const int lrow = tid >> 3;
    const int lc4  = (tid & 7) * 4;

    float Ck[4][4] = {};
    float Cv[4][4] = {};

    float4 a0, a1, bk0, bk1, bv0, bv1;

    auto loadA = [&](int k0, float4& r, int row) {
        const long m = m0 + row;
        r = *reinterpret_cast<const float4*>(&X[m * CC + k0 + lc4]);
        const int lkv = (int)m & (LKV - 1);
        if (lkv >= ZZ) {
            const float4 e = *reinterpret_cast<const float4*>(&ape[(long)(lkv - ZZ) * CC + k0 + lc4]);
            r.x += e.x; r.y += e.y; r.z += e.z; r.w += e.w;
        }
    };
    auto loadW = [&](const float* W, int k0, float4& r, int row) {
        r = *reinterpret_cast<const float4*>(&W[(long)(n0 + row) * CC + k0 + lc4]);
    };
    auto store = [&]() {
        sA [lrow     ][lc4 + 0] = f2tf(a0.x);  sA [lrow     ][lc4 + 1] = f2tf(a0.y);
        sA [lrow     ][lc4 + 2] = f2tf(a0.z);  sA [lrow     ][lc4 + 3] = f2tf(a0.w);
        sA [lrow + 32][lc4 + 0] = f2tf(a1.x);  sA [lrow + 32][lc4 + 1] = f2tf(a1.y);
        sA [lrow + 32][lc4 + 2] = f2tf(a1.z);  sA [lrow + 32][lc4 + 3] = f2tf(a1.w);
        sBk[lrow     ][lc4 + 0] = f2tf(bk0.x); sBk[lrow     ][lc4 + 1] = f2tf(bk0.y);
        sBk[lrow     ][lc4 + 2] = f2tf(bk0.z); sBk[lrow     ][lc4 + 3] = f2tf(bk0.w);
        sBk[lrow + 32][lc4 + 0] = f2tf(bk1.x); sBk[lrow + 32][lc4 + 1] = f2tf(bk1.y);
        sBk[lrow + 32][lc4 + 2] = f2tf(bk1.z); sBk[lrow + 32][lc4 + 3] = f2tf(bk1.w);
        sBv[lrow     ][lc4 + 0] = f2tf(bv0.x); sBv[lrow     ][lc4 + 1] = f2tf(bv0.y);
        sBv[lrow     ][lc4 + 2] = f2tf(bv0.z); sBv[lrow     ][lc4 + 3] = f2tf(bv0.w);
        sBv[lrow + 32][lc4 + 0] = f2tf(bv1.x); sBv[lrow + 32][lc4 + 1] = f2tf(bv1.y);
        sBv[lrow + 32][lc4 + 2] = f2tf(bv1.z); sBv[lrow + 32][lc4 + 3] = f2tf(bv1.w);
    };

    loadA(0, a0, lrow); loadA(0, a1, lrow + 32);
    loadW(Wk, 0, bk0, lrow); loadW(Wk, 0, bk1, lrow + 32);
    loadW(Wv, 0, bv0, lrow); loadW(Wv, 0, bv1, lrow + 32);
    store();
    __syncthreads();

    const int NK = CC / 32;
    for (int kt = 0; kt < NK; kt++) {
        // prefetch next k-chunk into registers BEFORE computing (overlap)
        if (kt + 1 < NK) {
            const int k0 = (kt + 1) * 32;
            loadA(k0, a0, lrow); loadA(k0, a1, lrow + 32);
            loadW(Wk, k0, bk0, lrow); loadW(Wk, k0, bk1, lrow + 32);
            loadW(Wv, k0, bv0, lrow); loadW(Wv, k0, bv1, lrow + 32);
        }

        #pragma unroll
        for (int ks = 0; ks < 4; ks++) {
            uint32_t a[4];
            const int rm = 16 * wm;
            a[0] = sA[rm + g    ][8 * ks + t];
            a[1] = sA[rm + g + 8][8 * ks + t];
            a[2] = sA[rm + g    ][8 * ks + t + 4];
            a[3] = sA[rm + g + 8][8 * ks + t + 4];
            #pragma unroll
            for (int nt = 0; nt < 4; nt++) {
                uint32_t bk[2], bv[2];
                bk[0] = sBk[32 * wn + 8 * nt + g][8 * ks + t];
                bk[1] = sBk[32 * wn + 8 * nt + g][8 * ks + t + 4];
                bv[0] = sBv[32 * wn + 8 * nt + g][8 * ks + t];
                bv[1] = sBv[32 * wn + 8 * nt + g][8 * ks + t + 4];
                mma_tf32(Ck[nt], a, bk);
                mma_tf32(Cv[nt], a, bv);
            }
        }

        if (kt + 1 < NK) {
            __syncthreads();   // everyone done reading this chunk
            store();
            __syncthreads();   // stores visible before next compute
        }
    }

    #pragma unroll
    for (int nt = 0; nt < 4; nt++) {
        const int r0 = m0 + 16 * wm + g;
        const int cc = n0 + 32 * wn + 8 * nt + 2 * t;
        *reinterpret_cast<float2*>(&Yk[(long)r0 * CC + cc])       = make_float2(Ck[nt][0], Ck[nt][1]);
        *reinterpret_cast<float2*>(&Yk[(long)(r0 + 8) * CC + cc]) = make_float2(Ck[nt][2], Ck[nt][3]);
        *reinterpret_cast<float2*>(&Yv[(long)r0 * CC + cc])       = make_float2(Cv[nt][0], Cv[nt][1]);
        *reinterpret_cast<float2*>(&Yv[(long)(r0 + 8) * CC + cc]) = make_float2(Cv[nt][2], Cv[nt][3]);
    }
}

// ---------------------------------------------------------------------------
// Flash attention with tf32 mma, softmax in exp2 domain, BK=64.
// smem: sK 18,432 + sV 20,480 = 38,912 B (< 48 KB).
// Block: BQ=128 q-rows, 8 warps; warp = 16 q-rows x all 64 kv cols of a tile.
// 64 kv tiles; online softmax fully in registers; Q frags preloaded.
// Positional bias loads hoisted above S MMAs to overlap DRAM latency.
// ---------------------------------------------------------------------------
__global__ __launch_bounds__(256)
void attn_mma(const float* __restrict__ Q, const float* __restrict__ Kp,
              const float* __restrict__ Vp, const float* __restrict__ pos,
              float* __restrict__ Xo)
{
    __shared__ uint32_t sK[2][64][36];   // [buf][kv][d] pad 36
    __shared__ uint32_t sV[2][64][40];   // [buf][kv][d] pad 40

    const int tid  = threadIdx.x;
    const int lane = tid & 31;
    const int w    = tid >> 5;          // 0..7, q-row block
    const int g    = lane >> 2;         // 0..7
    const int t    = lane & 3;          // 0..3
    const int b    = blockIdx.z;
    const int h    = blockIdx.y;
    const int q0   = blockIdx.x * 128;

    // scale * log2(e): softmax computed in exp2 domain
    const float qscale = 0.17677669529663687f * LOG2E;

    // ---- preload Q fragments (scaled), held for whole kernel ----
    uint32_t qf[4][4];
    {
        const long r0 = (long)(b * LQ + q0 + 16 * w + g) * CC + h * DD;
        const long r1 = r0 + 8L * CC;
        #pragma unroll
        for (int ks = 0; ks < 4; ks++) {
            qf[ks][0] = f2tf(qscale * Q[r0 + 8 * ks + t]);
            qf[ks][1] = f2tf(qscale * Q[r1 + 8 * ks + t]);
            qf[ks][2] = f2tf(qscale * Q[r0 + 8 * ks + t + 4]);
            qf[ks][3] = f2tf(qscale * Q[r1 + 8 * ks + t + 4]);
        }
    }

    float o[4][4] = {};            // O accum: [d-tile][reg], rows g/g+8
    float m0_ = -1e30f, m1_ = -1e30f;
    float l0_ = 0.0f,  l1_ = 0.0f;

    // tile loader (global -> regs), 64 rows x 32 cols per tile
    const int kr  = tid >> 3;          // 0..31 (rows kr, kr+32)
    const int kc4 = (tid & 7) * 4;     // 0,4,..28
    float4 kreg0, kreg1, vreg0, vreg1;

    auto loadTile = [&](int kbase) {
        const long g0 = (long)(b * LKV + kbase + kr) * CC + h * DD + kc4;
        const long g1 = g0 + 32L * CC;
        kreg0 = *reinterpret_cast<const float4*>(&Kp[g0]);
        kreg1 = *reinterpret_cast<const float4*>(&Kp[g1]);
        vreg0 = *reinterpret_cast<const float4*>(&Vp[g0]);
        vreg1 = *reinterpret_cast<const float4*>(&Vp[g1]);
    };
    auto storeTile = [&](int buf) {
        sK[buf][kr     ][kc4 + 0] = f2tf(kreg0.x); sK[buf][kr     ][kc4 + 1] = f2tf(kreg0.y);
        sK[buf][kr     ][kc4 + 2] = f2tf(kreg0.z); sK[buf][kr     ][kc4 + 3] = f2tf(kreg0.w);
        sK[buf][kr + 32][kc4 + 0] = f2tf(kreg1.x); sK[buf][kr + 32][kc4 + 1] = f2tf(kreg1.y);
        sK[buf][kr + 32][kc4 + 2] = f2tf(kreg1.z); sK[buf][kr + 32][kc4 + 3] = f2tf(kreg1.w);
        sV[buf][kr     ][kc4 + 0] = f2tf(vreg0.x); sV[buf][kr     ][kc4 + 1] = f2tf(vreg0.y);
        sV[buf][kr     ][kc4 + 2] = f2tf(vreg0.z); sV[buf][kr     ][kc4 + 3] = f2tf(vreg0.w);
        sV[buf][kr + 32][kc4 + 0] = f2tf(vreg1.x); sV[buf][kr + 32][kc4 + 1] = f2tf(vreg1.y);
        sV[buf][kr + 32][kc4 + 2] = f2tf(vreg1.z); sV[buf][kr + 32][kc4 + 3] = f2tf(vreg1.w);
    };

    loadTile(0);
    storeTile(0);

    const int NT = LKV / 64;   // 64 kv tiles

    for (int kt = 0; kt < NT; kt++) {
        const int cur = kt & 1;
        const int k0  = kt * 64;
        __syncthreads();

        // issue next-tile global loads early (latency overlap)
        if (kt + 1 < NT) loadTile(k0 + 64);

        // ---- hoisted positional-bias loads (kv < Z only): overlap with MMAs ----
        const bool inZ = (k0 < ZZ);
        float2 pf0[8], pf1[8];
        if (inZ) {
            const long pr0 = ((long)(h * LQ + q0 + 16 * w + g)) * ZZ + k0;
            const long pr1 = pr0 + 8L * ZZ;
            #pragma unroll
            for (int nt = 0; nt < 8; nt++) {
                pf0[nt] = *reinterpret_cast<const float2*>(&pos[pr0 + 8 * nt + 2 * t]);
                pf1[nt] = *reinterpret_cast<const float2*>(&pos[pr1 + 8 * nt + 2 * t]);
            }
        }

        // ---- S = Q K^T for this warp: 16 x 64 (log2 domain) ----
        float s[8][4] = {};
        #pragma unroll
        for (int nt = 0; nt < 8; nt++) {
            #pragma unroll
            for (int ks = 0; ks < 4; ks++) {
                uint32_t bk[2];
                bk[0] = sK[cur][8 * nt + g][8 * ks + t];
                bk[1] = sK[cur][8 * nt + g][8 * ks + t + 4];
                mma_tf32(s[nt], qf[ks], bk);
            }
        }

        // ---- apply positional bias, folded by log2e ----
        if (inZ) {
            #pragma unroll
            for (int nt = 0; nt < 8; nt++) {
                s[nt][0] = fmaf(pf0[nt].x, LOG2E, s[nt][0]);
                s[nt][1] = fmaf(pf0[nt].y, LOG2E, s[nt][1]);
                s[nt][2] = fmaf(pf1[nt].x, LOG2E, s[nt][2]);
                s[nt][3] = fmaf(pf1[nt].y, LOG2E, s[nt][3]);
            }
        }

        // ---- online softmax (register, 4-lane shuffle reductions) ----
        float mx0 = -1e30f, mx1 = -1e30f;
        #pragma unroll
        for (int nt = 0; nt < 8; nt++) {
            mx0 = fmaxf(mx0, fmaxf(s[nt][0], s[nt][1]));
            mx1 = fmaxf(mx1, fmaxf(s[nt][2], s[nt][3]));
        }
        mx0 = fmaxf(mx0, __shfl_xor_sync(0xffffffffu, mx0, 1));
        mx0 = fmaxf(mx0, __shfl_xor_sync(0xffffffffu, mx0, 2));
        mx1 = fmaxf(mx1, __shfl_xor_sync(0xffffffffu, mx1, 1));
        mx1 = fmaxf(mx1, __shfl_xor_sync(0xffffffffu, mx1, 2));

        const float mn0 = fmaxf(m0_, mx0);
        const float mn1 = fmaxf(m1_, mx1);
        const float al0 = ex2(m0_ - mn0);
        const float al1 = ex2(m1_ - mn1);
        m0_ = mn0; m1_ = mn1;

        float r0s = 0.0f, r1s = 0.0f;
        #pragma unroll
        for (int nt = 0; nt < 8; nt++) {
            s[nt][0] = ex2(s[nt][0] - mn0);
            s[nt][1] = ex2(s[nt][1] - mn0);
            s[nt][2] = ex2(s[nt][2] - mn1);
            s[nt][3] = ex2(s[nt][3] - mn1);
            r0s += s[nt][0] + s[nt][1];
            r1s += s[nt][2] + s[nt][3];
        }
        r0s += __shfl_xor_sync(0xffffffffu, r0s, 1);
        r0s += __shfl_xor_sync(0xffffffffu, r0s, 2);
        r1s += __shfl_xor_sync(0xffffffffu, r1s, 1);
        r1s += __shfl_xor_sync(0xffffffffu, r1s, 2);
        l0_ = l0_ * al0 + r0s;
        l1_ = l1_ * al1 + r1s;

        // ---- rescale O ----
        #pragma unroll
        for (int dt = 0; dt < 4; dt++) {
            o[dt][0] *= al0; o[dt][1] *= al0;
            o[dt][2] *= al1; o[dt][3] *= al1;
        }

        // ---- O += P V : remap P C-frags -> A-frags via shuffles ----
        const int src0 = (lane & ~3) | (t >> 1);
        const int src1 = (lane & ~3) | ((t >> 1) + 2);
        #pragma unroll
        for (int ks = 0; ks < 8; ks++) {
            const uint32_t p0 = f2tf(s[ks][0]);
            const uint32_t p1 = f2tf(s[ks][1]);
            const uint32_t p2 = f2tf(s[ks][2]);
            const uint32_t p3 = f2tf(s[ks][3]);
            uint32_t pa[4];
            {
                const uint32_t v00 = __shfl_sync(0xffffffffu, p0, src0);
                const uint32_t v01 = __shfl_sync(0xffffffffu, p1, src0);
                pa[0] = (t & 1) ? v01 : v00;
                const uint32_t v10 = __shfl_sync(0xffffffffu, p2, src0);
                const uint32_t v11 = __shfl_sync(0xffffffffu, p3, src0);
                pa[1] = (t & 1) ? v11 : v10;
                const uint32_t v20 = __shfl_sync(0xffffffffu, p0, src1);
                const uint32_t v21 = __shfl_sync(0xffffffffu, p1, src1);
                pa[2] = (t & 1) ? v21 : v20;
                const uint32_t v30 = __shfl_sync(0xffffffffu, p2, src1);
                const uint32_t v31 = __shfl_sync(0xffffffffu, p3, src1);
                pa[3] = (t & 1) ? v31 : v30;
            }
            #pragma unroll
            for (int dt = 0; dt < 4; dt++) {
                uint32_t bv[2];
                bv[0] = sV[cur][8 * ks + t    ][8 * dt + g];
                bv[1] = sV[cur][8 * ks + t + 4][8 * dt + g];
                mma_tf32(o[dt], pa, bv);
            }
        }

        // ---- stage next tile into the other buffer ----
        if (kt + 1 < NT) storeTile(cur ^ 1);
    }

    // ---- finalize ----
    const float inv0 = 1.0f / l0_;
    const float inv1 = 1.0f / l1_;
    const long orow = (long)(b * LQ + q0 + 16 * w + g) * CC + h * DD;
    #pragma unroll
    for (int dt = 0; dt < 4; dt++) {
        *reinterpret_cast<float2*>(&Xo[orow + 8 * dt + 2 * t]) =
            make_float2(o[dt][0] * inv0, o[dt][1] * inv0);
        *reinterpret_cast<float2*>(&Xo[orow + 8L * CC + 8 * dt + 2 * t]) =
            make_float2(o[dt][2] * inv1, o[dt][3] * inv1);
    }
}

// ---------------------------------------------------------------------------
// Launch
// ---------------------------------------------------------------------------
extern "C" void kernel_launch(void* const* d_in, const int* in_sizes, int n_in,
                              void* d_out, int out_size)
{
    const float* q        = (const float*)d_in[0];
    const float* kv       = (const float*)d_in[1];
    const float* q_ape    = (const float*)d_in[2];
    const float* k_ape    = (const float*)d_in[3];
    const float* attn_pos = (const float*)d_in[4];
    const float* Wq       = (const float*)d_in[5];
    const float* Wk       = (const float*)d_in[6];
    const float* Wv       = (const float*)d_in[7];
    const float* Wp       = (const float*)d_in[8];
    const float* bp       = (const float*)d_in[9];
    float* out = (float*)d_out;

    float *Qp, *Kp, *Vp, *Xo;
    cudaGetSymbolAddress((void**)&Qp, g_Q);
    cudaGetSymbolAddress((void**)&Kp, g_K);
    cudaGetSymbolAddress((void**)&Vp, g_V);
    cudaGetSymbolAddress((void**)&Xo, g_X);

    // Projections (APE fused); K and V fused into one pass over kv
    gemm_mma<1><<<dim3(CC / 64, (BB * LQ) / 64), 256>>>(q, q_ape, Wq, nullptr, Qp);
    gemm_kv_mma<<<dim3(CC / 64, (BB * LKV) / 64), 256>>>(kv, k_ape, Wk, Wv, Kp, Vp);

    // Flash attention (tf32 mma, exp2-domain softmax, BK=64)
    attn_mma<<<dim3(LQ / 128, HH, BB), 256>>>(Qp, Kp, Vp, attn_pos, Xo);

    // Output projection + bias
    gemm_mma<0><<<dim3(CC / 64, (BB * LQ) / 64), 256>>>(Xo, nullptr, Wp, bp, out);
}